// round 2
// baseline (speedup 1.0000x reference)
#include <cuda_runtime.h>

#define DIM     256
#define NTREES  512
#define TDEPTH  6
#define UNITS   16
#define LEAVES  64
#define BATCH   1024

#define BT      128                 // batch rows per block
#define NT      8                   // trees per block (one per warp)
#define KC      32                  // k-chunk
#define XPAD    34                  // x_s row stride: 17 (8B units) odd -> LDS.64 conflict-free
#define SELW    (NT * TDEPTH)       // 48 columns
#define NBLK    (NTREES / NT)       // 64
#define BBLK    (BATCH / BT)        // 8
#define OPAD    17                  // out_s row stride

// smem: x_s (128*34) + sel_s (16 kpairs * 96) + resp_s (8*16*64) + out_s (128*17)
#define XS_FLOATS   (BT * XPAD)                 // 4352
#define SELS_FLOATS (16 * 96)                   // 1536
#define RESP_FLOATS (NT * UNITS * LEAVES)       // 8192
#define OUT_FLOATS  (BT * OPAD)                 // 2176
#define SMEM_FLOATS (XS_FLOATS + SELS_FLOATS + RESP_FLOATS + OUT_FLOATS)
#define SMEM_BYTES  (SMEM_FLOATS * 4)           // 65024

__device__ float g_sel[DIM * NTREES * TDEPTH];          // 3 MB
__device__ float g_partial[NBLK * BATCH * UNITS];       // 4 MB

// ---- f32x2 packed helpers (ptxas won't auto-fuse these from C++) ----------
typedef unsigned long long u64;

__device__ __forceinline__ void ffma2(u64& d, u64 a, u64 b) {
    asm("fma.rn.f32x2 %0, %1, %2, %0;" : "+l"(d) : "l"(a), "l"(b));
}
__device__ __forceinline__ u64 fmul2(u64 a, u64 b) {
    u64 d; asm("mul.rn.f32x2 %0, %1, %2;" : "=l"(d) : "l"(a), "l"(b)); return d;
}
__device__ __forceinline__ u64 fpack2(float lo, float hi) {
    u64 d; asm("mov.b64 %0, {%1, %2};" : "=l"(d) : "f"(lo), "f"(hi)); return d;
}
__device__ __forceinline__ float fsum2(u64 v) {
    float lo, hi; asm("mov.b64 {%0, %1}, %2;" : "=f"(lo), "=f"(hi) : "l"(v));
    return lo + hi;
}

// ---------------------------------------------------------------------------
// Kernel 1: sparsemax along last axis (size 6).
// ---------------------------------------------------------------------------
__global__ void sparsemax6_kernel(const float* __restrict__ fsl) {
    int row = blockIdx.x * blockDim.x + threadIdx.x;
    if (row >= DIM * NTREES) return;
    const float* zp = fsl + (size_t)row * TDEPTH;
    float v[TDEPTH], s[TDEPTH];
#pragma unroll
    for (int j = 0; j < TDEPTH; j++) { v[j] = zp[j]; s[j] = v[j]; }
#pragma unroll
    for (int a = 0; a < TDEPTH - 1; a++)
#pragma unroll
        for (int b = 0; b < TDEPTH - 1 - a; b++)
            if (s[b] < s[b + 1]) { float t = s[b]; s[b] = s[b + 1]; s[b + 1] = t; }

    float cs[TDEPTH];
    float acc = 0.f;
    int cnt = 0;
#pragma unroll
    for (int j = 0; j < TDEPTH; j++) {
        acc += s[j];
        cs[j] = acc;
        if (s[j] * (float)(j + 1) > acc - 1.f) cnt++;
    }
    float csk = cs[0];
#pragma unroll
    for (int j = 1; j < TDEPTH; j++) if (cnt == j + 1) csk = cs[j];
    float tau = (csk - 1.f) / (float)cnt;

    float* op = g_sel + (size_t)row * TDEPTH;
#pragma unroll
    for (int j = 0; j < TDEPTH; j++) op[j] = fmaxf(v[j] - tau, 0.f);
}

// ---------------------------------------------------------------------------
// Kernel 2: fused fv-GEMM (FFMA2, k-paired) + gates + leaf products +
// response contraction (FFMA2) + per-block tree reduction.
// ---------------------------------------------------------------------------
__global__ __launch_bounds__(256, 2)
void node_kernel(const float* __restrict__ x,
                 const float* __restrict__ th,
                 const float* __restrict__ lt,
                 const float* __restrict__ resp) {
    extern __shared__ float sm[];
    float* x_s    = sm;                               // [BT][XPAD]
    float* sel_s  = x_s + XS_FLOATS;                  // [16 kp][48 cols * 2]
    float* resp_s = sel_s + SELS_FLOATS;              // [NT][UNITS][LEAVES]
    float* out_s  = resp_s + RESP_FLOATS;             // [BT][OPAD]

    const int tid  = threadIdx.x;
    const int w    = tid >> 5;
    const int l    = tid & 31;
    const int nblk = blockIdx.x;
    const int bblk = blockIdx.y;
    const int n0   = nblk * NT;
    const int b0   = bblk * BT;

    // Load response tile (8192 floats, float4-vectorized).
    {
        const float4* rg = (const float4*)(resp + (size_t)n0 * UNITS * LEAVES);
        for (int i = tid; i < RESP_FLOATS / 4; i += 256)
            ((float4*)resp_s)[i] = rg[i];
    }
    for (int i = tid; i < OUT_FLOATS; i += 256) out_s[i] = 0.f;

    // Per-warp tree parameters (uniform across the warp).
    float thv[TDEPTH], einv[TDEPTH];
#pragma unroll
    for (int d = 0; d < TDEPTH; d++) {
        thv[d]  = th[(n0 + w) * TDEPTH + d];
        einv[d] = __expf(-lt[(n0 + w) * TDEPTH + d]);
    }

    // f32x2 accumulators: (even-k partial, odd-k partial) per (row, depth).
    u64 fv2[4][TDEPTH];
#pragma unroll
    for (int r = 0; r < 4; r++)
#pragma unroll
        for (int d = 0; d < TDEPTH; d++) fv2[r][d] = 0ull;

    // --- GEMM mainloop ---
    for (int k0 = 0; k0 < DIM; k0 += KC) {
        __syncthreads();
        // x tile: BT x KC, coalesced float4 gmem loads, STS.64 x2 (8B aligned)
        for (int i = tid; i < BT * KC / 4; i += 256) {
            int b  = i >> 3;
            int kq = i & 7;
            float4 vx = *(const float4*)(x + (size_t)(b0 + b) * DIM + k0 + kq * 4);
            float* dst = x_s + b * XPAD + kq * 4;
            ((float2*)dst)[0] = make_float2(vx.x, vx.y);
            ((float2*)dst)[1] = make_float2(vx.z, vx.w);
        }
        // sel tile: KC x 48, re-staged interleaved:
        //   sel_s[(k>>1)*96 + c*2 + (k&1)]  (c = w*6+d)
        // so each warp's 6 (even,odd) f32x2 pairs are 12 contiguous floats.
        for (int i = tid; i < KC * SELW; i += 256) {
            int c = i % SELW;
            int k = i / SELW;
            float v = g_sel[(size_t)(k0 + k) * (NTREES * TDEPTH) + n0 * TDEPTH + c];
            sel_s[(k >> 1) * 96 + c * 2 + (k & 1)] = v;
        }
        __syncthreads();

#pragma unroll
        for (int kp = 0; kp < KC / 2; kp++) {
            u64 x2[4];
#pragma unroll
            for (int r = 0; r < 4; r++)
                x2[r] = *(const u64*)(x_s + (r * 32 + l) * XPAD + kp * 2);
            // 3 warp-uniform LDS.128 -> 6 f32x2 sel pairs
            const ulonglong2* sp = (const ulonglong2*)(sel_s + kp * 96 + w * 12);
            ulonglong2 s01 = sp[0], s23 = sp[1], s45 = sp[2];
#pragma unroll
            for (int r = 0; r < 4; r++) {
                ffma2(fv2[r][0], x2[r], s01.x);
                ffma2(fv2[r][1], x2[r], s01.y);
                ffma2(fv2[r][2], x2[r], s23.x);
                ffma2(fv2[r][3], x2[r], s23.y);
                ffma2(fv2[r][4], x2[r], s45.x);
                ffma2(fv2[r][5], x2[r], s45.y);
            }
        }
    }

    // --- Epilogue ---
    const ulonglong2* rp2 = (const ulonglong2*)(resp_s + w * (UNITS * LEAVES));
#pragma unroll
    for (int r = 0; r < 4; r++) {
        float gp[TDEPTH], gn[TDEPTH];
#pragma unroll
        for (int d = 0; d < TDEPTH; d++) {
            float fvv = fsum2(fv2[r][d]);                 // even + odd partials
            float t = (fvv - thv[d]) * einv[d];
            float g = __saturatef(0.5f * t + 0.5f);       // gate for bit==0
            gp[d] = g;
            gn[d] = 1.f - g;                              // gate for bit==1
        }
        // Leaf weights: w[c] = wlo[c&3] * whi[c>>2]
        float wlo0 = gp[0] * gp[1];
        float wlo1 = gn[0] * gp[1];
        float wlo2 = gp[0] * gn[1];
        float wlo3 = gn[0] * gn[1];
        u64 wlo01 = fpack2(wlo0, wlo1);
        u64 wlo23 = fpack2(wlo2, wlo3);

        float a2[2] = { gp[2], gn[2] };
        float a3[4], a4[8], whi[16];
#pragma unroll
        for (int j = 0; j < 2; j++) { a3[j] = a2[j] * gp[3]; a3[j + 2] = a2[j] * gn[3]; }
#pragma unroll
        for (int j = 0; j < 4; j++) { a4[j] = a3[j] * gp[4]; a4[j + 4] = a3[j] * gn[4]; }
#pragma unroll
        for (int j = 0; j < 8; j++) { whi[j] = a4[j] * gp[5]; whi[j + 8] = a4[j] * gn[5]; }

        u64 oacc2[UNITS];
#pragma unroll
        for (int u = 0; u < UNITS; u++) oacc2[u] = 0ull;
#pragma unroll 4
        for (int hi = 0; hi < 16; hi++) {
            u64 whi2 = fpack2(whi[hi], whi[hi]);
            u64 w01 = fmul2(wlo01, whi2);
            u64 w23 = fmul2(wlo23, whi2);
#pragma unroll
            for (int u = 0; u < UNITS; u++) {
                ulonglong2 rv = rp2[u * 16 + hi];         // warp-uniform LDS.128
                ffma2(oacc2[u], w01, rv.x);
                ffma2(oacc2[u], w23, rv.y);
            }
        }
        int row = r * 32 + l;
#pragma unroll
        for (int u = 0; u < UNITS; u++)
            atomicAdd(out_s + row * OPAD + u, fsum2(oacc2[u]));
    }

    __syncthreads();
    for (int i = tid; i < BT * UNITS; i += 256) {
        int b = i >> 4, u = i & 15;
        g_partial[((size_t)nblk * BATCH + b0 + b) * UNITS + u] = out_s[b * OPAD + u];
    }
}

// ---------------------------------------------------------------------------
// Kernel 3: reduce the 64 n-block partials, apply mean over trees.
// ---------------------------------------------------------------------------
__global__ void reduce_kernel(float* __restrict__ out) {
    int i = blockIdx.x * blockDim.x + threadIdx.x;   // 0 .. 16383
    float acc = 0.f;
#pragma unroll 8
    for (int nb = 0; nb < NBLK; nb++)
        acc += g_partial[(size_t)nb * BATCH * UNITS + i];
    out[i] = acc * (1.f / (float)NTREES);
}

// ---------------------------------------------------------------------------
extern "C" void kernel_launch(void* const* d_in, const int* in_sizes, int n_in,
                              void* d_out, int out_size) {
    const float* x    = (const float*)d_in[0];   // (1024, 256)
    const float* fsl  = (const float*)d_in[1];   // (256, 512, 6)
    const float* th   = (const float*)d_in[2];   // (512, 6)
    const float* lt   = (const float*)d_in[3];   // (512, 6)
    const float* resp = (const float*)d_in[4];   // (512, 16, 64)
    float* out = (float*)d_out;                  // (1024, 16)

    cudaFuncSetAttribute(node_kernel,
                         cudaFuncAttributeMaxDynamicSharedMemorySize, SMEM_BYTES);

    sparsemax6_kernel<<<(DIM * NTREES + 255) / 256, 256>>>(fsl);
    dim3 grid(NBLK, BBLK);
    node_kernel<<<grid, 256, SMEM_BYTES>>>(x, th, lt, resp);
    reduce_kernel<<<BATCH * UNITS / 256, 256>>>(out);
}

// round 4
// speedup vs baseline: 1.0236x; 1.0236x over previous
#include <cuda_runtime.h>
#include <cuda_fp16.h>
#include <mma.h>
#include <cstdint>

using namespace nvcuda;

// ---------------- problem dims ----------------
#define DIM     256
#define NTREES  512
#define TDEPTH  6
#define UNITS   16
#define LEAVES  64
#define BATCH   1024
#define NJ      (NTREES * TDEPTH)       // 3072 columns (j = n*6+d)

// ---------------- device scratch ----------------
__device__ __align__(16) __half g_xhi[BATCH * DIM];
__device__ __align__(16) __half g_xlo[BATCH * DIM];
__device__ __align__(16) __half g_shi[DIM * NJ];
__device__ __align__(16) __half g_slo[DIM * NJ];
__device__ __align__(16) float  g_gatesT[(size_t)NJ * 2 * BATCH];  // 25 MB, [j*2+p][b]
__device__ float g_partial[64 * BATCH * UNITS];                    // 4 MB

// ---------------------------------------------------------------------------
// Kernel 1: sparsemax over last axis (6), emitting fp16 hi/lo selector splits
// in [k][j] layout (j = n*6+d) ready for the GEMM B operand.
// ---------------------------------------------------------------------------
__global__ void sparsemax6_kernel(const float* __restrict__ fsl) {
    int row = blockIdx.x * blockDim.x + threadIdx.x;    // row = i*512 + n
    if (row >= DIM * NTREES) return;
    const float* zp = fsl + (size_t)row * TDEPTH;
    float v[TDEPTH], s[TDEPTH];
#pragma unroll
    for (int j = 0; j < TDEPTH; j++) { v[j] = zp[j]; s[j] = v[j]; }
#pragma unroll
    for (int a = 0; a < TDEPTH - 1; a++)
#pragma unroll
        for (int b = 0; b < TDEPTH - 1 - a; b++)
            if (s[b] < s[b + 1]) { float t = s[b]; s[b] = s[b + 1]; s[b + 1] = t; }
    float cs[TDEPTH], acc = 0.f; int cnt = 0;
#pragma unroll
    for (int j = 0; j < TDEPTH; j++) {
        acc += s[j]; cs[j] = acc;
        if (s[j] * (float)(j + 1) > acc - 1.f) cnt++;
    }
    float csk = cs[0];
#pragma unroll
    for (int j = 1; j < TDEPTH; j++) if (cnt == j + 1) csk = cs[j];
    float tau = (csk - 1.f) / (float)cnt;

    int i = row >> 9, n = row & 511;
    size_t base = (size_t)i * NJ + (size_t)n * TDEPTH;
#pragma unroll
    for (int j = 0; j < TDEPTH; j++) {
        float sv = fmaxf(v[j] - tau, 0.f);
        __half hi = __float2half_rn(sv);
        g_shi[base + j] = hi;
        g_slo[base + j] = __float2half_rn(sv - __half2float(hi));
    }
}

// ---------------------------------------------------------------------------
// Kernel 2: split x into fp16 hi/lo.
// ---------------------------------------------------------------------------
__global__ void splitx_kernel(const float* __restrict__ x) {
    int i = blockIdx.x * blockDim.x + threadIdx.x;
    if (i >= BATCH * DIM) return;
    float v = x[i];
    __half hi = __float2half_rn(v);
    g_xhi[i] = hi;
    g_xlo[i] = __float2half_rn(v - __half2float(hi));
}

// ---------------------------------------------------------------------------
// Kernel 3: fv GEMM via wmma (fp16 3-term split, fp32 accum), fused gate
// epilogue writing g_gatesT[j*2+p][b].
// Block: 256 thr = 8 warps (4 M x 2 N), tile M=128(batch) x N=64(j), warp
// tile 32x32 = 2x2 fragments. K staged in 64-chunks via smem.
// ---------------------------------------------------------------------------
#define GM 128
#define GN 64
#define GK 64
#define A_LDM 72                         // halves; 144 B rows (16B aligned)
#define C_LDM 132                        // floats; C stored transposed [j][b]

#define S_A   0                          // 128*72*2 = 18432 B
#define S_B   18432                      // 64*72*2  =  9216 B
#define S_C   0                          // reuse: 64*132*4 = 33792 B
#define S_TH  33792                      // 64 floats
#define S_EI  (33792 + 256)              // 64 floats
#define S_TOT (33792 + 512)              // 34304 B (< 48KB default)

__global__ __launch_bounds__(256, 2)
void fv_mma_kernel(const float* __restrict__ th, const float* __restrict__ lt) {
    extern __shared__ char smem[];
    __half* As = (__half*)(smem + S_A);
    __half* Bs = (__half*)(smem + S_B);
    float*  Cs = (float*)(smem + S_C);
    float*  ths = (float*)(smem + S_TH);
    float*  ein = (float*)(smem + S_EI);

    const int tid = threadIdx.x;
    const int w   = tid >> 5;
    const int wm  = w & 3;               // M warp index (0..3)
    const int wn  = w >> 2;              // N warp index (0..1)
    const int j0  = blockIdx.x * GN;
    const int b0  = blockIdx.y * GM;

    if (tid < GN) {
        ths[tid] = th[j0 + tid];
        ein[tid] = __expf(-lt[j0 + tid]);
    }

    wmma::fragment<wmma::accumulator, 16, 16, 16, float> c[2][2];
#pragma unroll
    for (int i = 0; i < 2; i++)
#pragma unroll
        for (int j = 0; j < 2; j++) wmma::fill_fragment(c[i][j], 0.f);

#pragma unroll 1
    for (int seg = 0; seg < 3; seg++) {
        const __half* xs = (seg == 1) ? g_xlo : g_xhi;
        const __half* ss = (seg == 2) ? g_slo : g_shi;
#pragma unroll 1
        for (int ch = 0; ch < DIM / GK; ch++) {
            const int k0 = ch * GK;
            __syncthreads();             // previous iter's fragment loads done
            // A tile: 128 x 64 halves (8-half vector loads/stores)
            for (int i = tid; i < GM * 8; i += 256) {
                int r = i >> 3, cq = i & 7;
                float4 v = *(const float4*)(xs + (size_t)(b0 + r) * DIM + k0 + cq * 8);
                *(float4*)(As + r * A_LDM + cq * 8) = v;
            }
            // B tile: 64 x 64 halves
            for (int i = tid; i < GK * 8; i += 256) {
                int r = i >> 3, cq = i & 7;
                float4 v = *(const float4*)(ss + (size_t)(k0 + r) * NJ + j0 + cq * 8);
                *(float4*)(Bs + r * A_LDM + cq * 8) = v;
            }
            __syncthreads();

#pragma unroll
            for (int kk = 0; kk < GK / 16; kk++) {
                wmma::fragment<wmma::matrix_a, 16, 16, 16, __half, wmma::row_major> a[2];
                wmma::fragment<wmma::matrix_b, 16, 16, 16, __half, wmma::row_major> b[2];
#pragma unroll
                for (int i = 0; i < 2; i++)
                    wmma::load_matrix_sync(a[i], As + (wm * 32 + i * 16) * A_LDM + kk * 16, A_LDM);
#pragma unroll
                for (int j = 0; j < 2; j++)
                    wmma::load_matrix_sync(b[j], Bs + (kk * 16) * A_LDM + wn * 32 + j * 16, A_LDM);
#pragma unroll
                for (int i = 0; i < 2; i++)
#pragma unroll
                    for (int j = 0; j < 2; j++)
                        wmma::mma_sync(c[i][j], a[i], b[j], c[i][j]);
            }
        }
    }

    // Epilogue: store C transposed [j_local][b_local] (conflict-free reads).
    __syncthreads();
#pragma unroll
    for (int i = 0; i < 2; i++)
#pragma unroll
        for (int j = 0; j < 2; j++)
            wmma::store_matrix_sync(Cs + (size_t)(wn * 32 + j * 16) * C_LDM + wm * 32 + i * 16,
                                    c[i][j], C_LDM, wmma::mem_col_major);
    __syncthreads();

    for (int i = tid; i < GN * GM; i += 256) {
        int jl = i >> 7, bl = i & 127;   // lanes cover contiguous b
        float fv = Cs[jl * C_LDM + bl];
        float t  = (fv - ths[jl]) * ein[jl];
        float gp = __saturatef(fmaf(0.5f, t, 0.5f));
        float* gb = g_gatesT + ((size_t)(j0 + jl) * 2) * BATCH + b0 + bl;
        gb[0]     = gp;                  // row 2j   (bit==0 branch)
        gb[BATCH] = 1.f - gp;            // row 2j+1 (bit==1 branch)
    }
}

// ---------------------------------------------------------------------------
// Kernel 4: response contraction (R1-proven epilogue).
// Block: 128 batch x 8 trees; warp = tree; lane handles rows r*32+l.
// ---------------------------------------------------------------------------
#define BT   128
#define NT   8
#define NBLK (NTREES / NT)              // 64
#define BBLK (BATCH / BT)               // 8
#define OPAD 17
#define GROWS (NT * TDEPTH * 2)         // 96 gate rows per block

#define GATE_F (GROWS * BT)             // 12288
#define RESP_F (NT * UNITS * LEAVES)    // 8192
#define OUT_F  (BT * OPAD)              // 2176
#define RSMEM  ((GATE_F + RESP_F + OUT_F) * 4)   // 90624 B

__global__ __launch_bounds__(256, 2)
void resp_kernel(const float* __restrict__ resp) {
    extern __shared__ float sm[];
    float* gate_s = sm;                     // [96][128]
    float* resp_s = gate_s + GATE_F;        // [8][16][64]
    float* out_s  = resp_s + RESP_F;        // [128][17]

    const int tid  = threadIdx.x;
    const int w    = tid >> 5;
    const int l    = tid & 31;
    const int n0   = blockIdx.x * NT;
    const int b0   = blockIdx.y * BT;

    // gate tile: rows n0*12 .. +95 of g_gatesT, cols b0..b0+127
    for (int i = tid; i < GROWS * (BT / 4); i += 256) {
        int gr = i >> 5, c4 = i & 31;
        float4 v = *(const float4*)(g_gatesT + (size_t)(n0 * 12 + gr) * BATCH + b0 + c4 * 4);
        *(float4*)(gate_s + gr * BT + c4 * 4) = v;
    }
    {
        const float4* rg = (const float4*)(resp + (size_t)n0 * UNITS * LEAVES);
        for (int i = tid; i < RESP_F / 4; i += 256) ((float4*)resp_s)[i] = rg[i];
    }
    for (int i = tid; i < OUT_F; i += 256) out_s[i] = 0.f;
    __syncthreads();

    const float4* rp = (const float4*)(resp_s + w * (UNITS * LEAVES));
#pragma unroll
    for (int r = 0; r < 4; r++) {
        int row = r * 32 + l;
        float gp[TDEPTH], gn[TDEPTH];
#pragma unroll
        for (int d = 0; d < TDEPTH; d++) {
            gp[d] = gate_s[(w * 12 + 2 * d) * BT + row];
            gn[d] = gate_s[(w * 12 + 2 * d + 1) * BT + row];
        }
        float wlo[4];
        wlo[0] = gp[0] * gp[1];
        wlo[1] = gn[0] * gp[1];
        wlo[2] = gp[0] * gn[1];
        wlo[3] = gn[0] * gn[1];
        float a2[2] = { gp[2], gn[2] };
        float a3[4], a4[8], whi[16];
#pragma unroll
        for (int j = 0; j < 2; j++) { a3[j] = a2[j] * gp[3]; a3[j + 2] = a2[j] * gn[3]; }
#pragma unroll
        for (int j = 0; j < 4; j++) { a4[j] = a3[j] * gp[4]; a4[j + 4] = a3[j] * gn[4]; }
#pragma unroll
        for (int j = 0; j < 8; j++) { whi[j] = a4[j] * gp[5]; whi[j + 8] = a4[j] * gn[5]; }

        float oacc[UNITS];
#pragma unroll
        for (int u = 0; u < UNITS; u++) oacc[u] = 0.f;
#pragma unroll 4
        for (int hi = 0; hi < 16; hi++) {
            float wh = whi[hi];
            float w0 = wlo[0] * wh, w1 = wlo[1] * wh;
            float w2 = wlo[2] * wh, w3 = wlo[3] * wh;
#pragma unroll
            for (int u = 0; u < UNITS; u++) {
                float4 rv = rp[u * 16 + hi];          // warp-uniform LDS.128
                oacc[u] += w0 * rv.x + w1 * rv.y + w2 * rv.z + w3 * rv.w;
            }
        }
#pragma unroll
        for (int u = 0; u < UNITS; u++)
            atomicAdd(out_s + row * OPAD + u, oacc[u]);
    }

    __syncthreads();
    for (int i = tid; i < BT * UNITS; i += 256) {
        int b = i >> 4, u = i & 15;
        g_partial[((size_t)blockIdx.x * BATCH + b0 + b) * UNITS + u] = out_s[b * OPAD + u];
    }
}

// ---------------------------------------------------------------------------
// Kernel 5: reduce n-block partials, mean over trees.
// ---------------------------------------------------------------------------
__global__ void reduce_kernel(float* __restrict__ out) {
    int i = blockIdx.x * blockDim.x + threadIdx.x;
    float acc = 0.f;
#pragma unroll 8
    for (int nb = 0; nb < NBLK; nb++)
        acc += g_partial[(size_t)nb * BATCH * UNITS + i];
    out[i] = acc * (1.f / (float)NTREES);
}

// ---------------------------------------------------------------------------
extern "C" void kernel_launch(void* const* d_in, const int* in_sizes, int n_in,
                              void* d_out, int out_size) {
    const float* x    = (const float*)d_in[0];   // (1024, 256)
    const float* fsl  = (const float*)d_in[1];   // (256, 512, 6)
    const float* th   = (const float*)d_in[2];   // (512, 6)
    const float* lt   = (const float*)d_in[3];   // (512, 6)
    const float* resp = (const float*)d_in[4];   // (512, 16, 64)
    float* out = (float*)d_out;                  // (1024, 16)

    cudaFuncSetAttribute(resp_kernel,
                         cudaFuncAttributeMaxDynamicSharedMemorySize, RSMEM);

    sparsemax6_kernel<<<(DIM * NTREES + 255) / 256, 256>>>(fsl);
    splitx_kernel<<<(BATCH * DIM + 255) / 256, 256>>>(x);
    fv_mma_kernel<<<dim3(NJ / GN, BATCH / GM), 256, S_TOT>>>(th, lt);
    resp_kernel<<<dim3(NBLK, BBLK), 256, RSMEM>>>(resp);
    reduce_kernel<<<BATCH * UNITS / 256, 256>>>(out);
}

// round 5
// speedup vs baseline: 1.3593x; 1.3279x over previous
#include <cuda_runtime.h>
#include <cuda_fp16.h>
#include <mma.h>
#include <cstdint>

using namespace nvcuda;

// ---------------- problem dims ----------------
#define DIM     256
#define NTREES  512
#define TDEPTH  6
#define UNITS   16
#define LEAVES  64
#define BATCH   1024
#define NJ      (NTREES * TDEPTH)       // 3072 columns (j = n*6+d)

// ---------------- device scratch ----------------
__device__ __align__(16) __half g_xhi[BATCH * DIM];
__device__ __align__(16) __half g_xlo[BATCH * DIM];
__device__ __align__(16) __half g_shi[DIM * NJ];
__device__ __align__(16) __half g_slo[DIM * NJ];
__device__ __align__(16) float  g_gatesT[(size_t)NJ * 2 * BATCH];  // 25 MB, [j*2+p][b]
__device__ float g_partial[64 * BATCH * UNITS];                    // 4 MB

__device__ __forceinline__ uint32_t h2u(__half2 h) {
    return *reinterpret_cast<uint32_t*>(&h);
}

// ---------------------------------------------------------------------------
// Kernel 1: sparsemax over last axis (6), emitting fp16 hi/lo selector splits
// in [k][j] layout (j = n*6+d) ready for the GEMM B operand.
// ---------------------------------------------------------------------------
__global__ void sparsemax6_kernel(const float* __restrict__ fsl) {
    int row = blockIdx.x * blockDim.x + threadIdx.x;    // row = i*512 + n
    if (row >= DIM * NTREES) return;
    const float* zp = fsl + (size_t)row * TDEPTH;
    float v[TDEPTH], s[TDEPTH];
#pragma unroll
    for (int j = 0; j < TDEPTH; j++) { v[j] = zp[j]; s[j] = v[j]; }
#pragma unroll
    for (int a = 0; a < TDEPTH - 1; a++)
#pragma unroll
        for (int b = 0; b < TDEPTH - 1 - a; b++)
            if (s[b] < s[b + 1]) { float t = s[b]; s[b] = s[b + 1]; s[b + 1] = t; }
    float cs[TDEPTH], acc = 0.f; int cnt = 0;
#pragma unroll
    for (int j = 0; j < TDEPTH; j++) {
        acc += s[j]; cs[j] = acc;
        if (s[j] * (float)(j + 1) > acc - 1.f) cnt++;
    }
    float csk = cs[0];
#pragma unroll
    for (int j = 1; j < TDEPTH; j++) if (cnt == j + 1) csk = cs[j];
    float tau = (csk - 1.f) / (float)cnt;

    int i = row >> 9, n = row & 511;
    size_t base = (size_t)i * NJ + (size_t)n * TDEPTH;
#pragma unroll
    for (int j = 0; j < TDEPTH; j++) {
        float sv = fmaxf(v[j] - tau, 0.f);
        __half hi = __float2half_rn(sv);
        g_shi[base + j] = hi;
        g_slo[base + j] = __float2half_rn(sv - __half2float(hi));
    }
}

// ---------------------------------------------------------------------------
// Kernel 2: split x into fp16 hi/lo.
// ---------------------------------------------------------------------------
__global__ void splitx_kernel(const float* __restrict__ x) {
    int i = blockIdx.x * blockDim.x + threadIdx.x;
    if (i >= BATCH * DIM) return;
    float v = x[i];
    __half hi = __float2half_rn(v);
    g_xhi[i] = hi;
    g_xlo[i] = __float2half_rn(v - __half2float(hi));
}

// ---------------------------------------------------------------------------
// Kernel 3: fv GEMM via wmma (fp16 3-term split, fp32 accum), fused gate
// epilogue writing g_gatesT[j*2+p][b].  (unchanged from R4 — validated)
// ---------------------------------------------------------------------------
#define GM 128
#define GN 64
#define GK 64
#define A_LDM 72
#define C_LDM 132

#define S_A   0
#define S_B   18432
#define S_C   0
#define S_TH  33792
#define S_EI  (33792 + 256)
#define S_TOT (33792 + 512)

__global__ __launch_bounds__(256, 2)
void fv_mma_kernel(const float* __restrict__ th, const float* __restrict__ lt) {
    extern __shared__ char smem[];
    __half* As = (__half*)(smem + S_A);
    __half* Bs = (__half*)(smem + S_B);
    float*  Cs = (float*)(smem + S_C);
    float*  ths = (float*)(smem + S_TH);
    float*  ein = (float*)(smem + S_EI);

    const int tid = threadIdx.x;
    const int w   = tid >> 5;
    const int wm  = w & 3;
    const int wn  = w >> 2;
    const int j0  = blockIdx.x * GN;
    const int b0  = blockIdx.y * GM;

    if (tid < GN) {
        ths[tid] = th[j0 + tid];
        ein[tid] = __expf(-lt[j0 + tid]);
    }

    wmma::fragment<wmma::accumulator, 16, 16, 16, float> c[2][2];
#pragma unroll
    for (int i = 0; i < 2; i++)
#pragma unroll
        for (int j = 0; j < 2; j++) wmma::fill_fragment(c[i][j], 0.f);

#pragma unroll 1
    for (int seg = 0; seg < 3; seg++) {
        const __half* xs = (seg == 1) ? g_xlo : g_xhi;
        const __half* ss = (seg == 2) ? g_slo : g_shi;
#pragma unroll 1
        for (int ch = 0; ch < DIM / GK; ch++) {
            const int k0 = ch * GK;
            __syncthreads();
            for (int i = tid; i < GM * 8; i += 256) {
                int r = i >> 3, cq = i & 7;
                float4 v = *(const float4*)(xs + (size_t)(b0 + r) * DIM + k0 + cq * 8);
                *(float4*)(As + r * A_LDM + cq * 8) = v;
            }
            for (int i = tid; i < GK * 8; i += 256) {
                int r = i >> 3, cq = i & 7;
                float4 v = *(const float4*)(ss + (size_t)(k0 + r) * NJ + j0 + cq * 8);
                *(float4*)(Bs + r * A_LDM + cq * 8) = v;
            }
            __syncthreads();

#pragma unroll
            for (int kk = 0; kk < GK / 16; kk++) {
                wmma::fragment<wmma::matrix_a, 16, 16, 16, __half, wmma::row_major> a[2];
                wmma::fragment<wmma::matrix_b, 16, 16, 16, __half, wmma::row_major> b[2];
#pragma unroll
                for (int i = 0; i < 2; i++)
                    wmma::load_matrix_sync(a[i], As + (wm * 32 + i * 16) * A_LDM + kk * 16, A_LDM);
#pragma unroll
                for (int j = 0; j < 2; j++)
                    wmma::load_matrix_sync(b[j], Bs + (kk * 16) * A_LDM + wn * 32 + j * 16, A_LDM);
#pragma unroll
                for (int i = 0; i < 2; i++)
#pragma unroll
                    for (int j = 0; j < 2; j++)
                        wmma::mma_sync(c[i][j], a[i], b[j], c[i][j]);
            }
        }
    }

    __syncthreads();
#pragma unroll
    for (int i = 0; i < 2; i++)
#pragma unroll
        for (int j = 0; j < 2; j++)
            wmma::store_matrix_sync(Cs + (size_t)(wn * 32 + j * 16) * C_LDM + wm * 32 + i * 16,
                                    c[i][j], C_LDM, wmma::mem_col_major);
    __syncthreads();

    for (int i = tid; i < GN * GM; i += 256) {
        int jl = i >> 7, bl = i & 127;
        float fv = Cs[jl * C_LDM + bl];
        float t  = (fv - ths[jl]) * ein[jl];
        float gp = __saturatef(fmaf(0.5f, t, 0.5f));
        float* gb = g_gatesT + ((size_t)(j0 + jl) * 2) * BATCH + b0 + bl;
        gb[0]     = gp;
        gb[BATCH] = 1.f - gp;
    }
}

// ---------------------------------------------------------------------------
// Kernel 4: response contraction via wmma.
// Block = 128 batch rows x 8 trees, 256 threads (8 warps).
// For each tree: build W[128][64] (leaf weights, fp16 hi/lo split) in smem,
// then accumulate  out += Whi@Rhi + Wlo@Rhi + Whi@Rlo  into persistent
// accumulator fragments (warp w owns rows w*16..w*16+15, all 16 units).
// ---------------------------------------------------------------------------
#define BT    128
#define NT    8
#define NBLK  (NTREES / NT)             // 64
#define BBLK  (BATCH / BT)              // 8
#define W_LDM 72                        // halves per W row (144 B, mult of 8)
#define R_LDM 72                        // halves per R row

#define RS_WHI 0                        // 128*72*2 = 18432
#define RS_WLO 18432                    // 18432
#define RS_RHI 36864                    // 8*16*72*2 = 18432
#define RS_RLO 55296                    // 18432
#define RSMEM  73728

__global__ __launch_bounds__(256, 2)
void resp_mma_kernel(const float* __restrict__ resp) {
    extern __shared__ char smem[];
    __half* Whi_s = (__half*)(smem + RS_WHI);
    __half* Wlo_s = (__half*)(smem + RS_WLO);
    __half* rhi_s = (__half*)(smem + RS_RHI);
    __half* rlo_s = (__half*)(smem + RS_RLO);

    const int tid = threadIdx.x;
    const int w   = tid >> 5;
    const int n0  = blockIdx.x * NT;
    const int b0  = blockIdx.y * BT;
    const int bl  = tid & 127;          // W-build: batch row
    const int h   = tid >> 7;           // W-build: leaf half (bit5)

    // Stage response (8 trees x 16 u x 64 c) as fp16 hi/lo, padded ldm=72.
    for (int i = tid; i < NT * UNITS * LEAVES; i += 256) {
        int t = i >> 10, rem = i & 1023;          // rem = u*64 + c
        int u = rem >> 6, c = rem & 63;
        float v = resp[(size_t)(n0 + t) * (UNITS * LEAVES) + rem];
        __half hi = __float2half_rn(v);
        rhi_s[(t * UNITS + u) * R_LDM + c] = hi;
        rlo_s[(t * UNITS + u) * R_LDM + c] = __float2half_rn(v - __half2float(hi));
    }

    wmma::fragment<wmma::accumulator, 16, 16, 16, float> cfrag;
    wmma::fill_fragment(cfrag, 0.f);
    __syncthreads();

#pragma unroll 1
    for (int t = 0; t < NT; t++) {
        // ---- Build W (leaf weights) for tree n0+t: thread covers row bl,
        //      leaves [32h, 32h+32). gates: coalesced LDG across lanes. ----
        {
            const float* gbase = g_gatesT + (size_t)((n0 + t) * 12) * BATCH + b0 + bl;
            float gp[TDEPTH], gn[TDEPTH];
#pragma unroll
            for (int d = 0; d < TDEPTH; d++) {
                gp[d] = gbase[(size_t)(2 * d) * BATCH];
                gn[d] = gbase[(size_t)(2 * d + 1) * BATCH];
            }
            float wlo[4];
            wlo[0] = gp[0] * gp[1];
            wlo[1] = gn[0] * gp[1];
            wlo[2] = gp[0] * gn[1];
            wlo[3] = gn[0] * gn[1];
            float g5 = h ? gn[5] : gp[5];
            float a3[4], whi8[8];
            a3[0] = gp[2] * gp[3]; a3[1] = gn[2] * gp[3];
            a3[2] = gp[2] * gn[3]; a3[3] = gn[2] * gn[3];
#pragma unroll
            for (int j = 0; j < 4; j++) {
                whi8[j]     = a3[j] * gp[4] * g5;
                whi8[j + 4] = a3[j] * gn[4] * g5;
            }

            uint32_t uhi[16], ulo[16];
#pragma unroll
            for (int j = 0; j < 8; j++) {
                float w0 = wlo[0] * whi8[j], w1 = wlo[1] * whi8[j];
                float w2 = wlo[2] * whi8[j], w3 = wlo[3] * whi8[j];
                __half2 h01 = __floats2half2_rn(w0, w1);
                __half2 h23 = __floats2half2_rn(w2, w3);
                __half2 l01 = __floats2half2_rn(w0 - __low2float(h01),
                                                w1 - __high2float(h01));
                __half2 l23 = __floats2half2_rn(w2 - __low2float(h23),
                                                w3 - __high2float(h23));
                uhi[j * 2] = h2u(h01); uhi[j * 2 + 1] = h2u(h23);
                ulo[j * 2] = h2u(l01); ulo[j * 2 + 1] = h2u(l23);
            }
            uint4* dh = (uint4*)(Whi_s + bl * W_LDM + h * 32);
            uint4* dl = (uint4*)(Wlo_s + bl * W_LDM + h * 32);
#pragma unroll
            for (int q = 0; q < 4; q++) {
                dh[q] = make_uint4(uhi[q * 4], uhi[q * 4 + 1], uhi[q * 4 + 2], uhi[q * 4 + 3]);
                dl[q] = make_uint4(ulo[q * 4], ulo[q * 4 + 1], ulo[q * 4 + 2], ulo[q * 4 + 3]);
            }
        }
        __syncthreads();

        // ---- MMA: warp w owns batch rows w*16..+15 x all 16 units. ----
        const __half* rh = rhi_s + t * UNITS * R_LDM;
        const __half* rl = rlo_s + t * UNITS * R_LDM;
#pragma unroll
        for (int kk = 0; kk < LEAVES / 16; kk++) {
            wmma::fragment<wmma::matrix_a, 16, 16, 16, __half, wmma::row_major> ahi, alo;
            wmma::fragment<wmma::matrix_b, 16, 16, 16, __half, wmma::col_major> bhi, blo;
            wmma::load_matrix_sync(ahi, Whi_s + (w * 16) * W_LDM + kk * 16, W_LDM);
            wmma::load_matrix_sync(alo, Wlo_s + (w * 16) * W_LDM + kk * 16, W_LDM);
            wmma::load_matrix_sync(bhi, rh + kk * 16, R_LDM);
            wmma::load_matrix_sync(blo, rl + kk * 16, R_LDM);
            wmma::mma_sync(cfrag, ahi, bhi, cfrag);
            wmma::mma_sync(cfrag, alo, bhi, cfrag);
            wmma::mma_sync(cfrag, ahi, blo, cfrag);
        }
        __syncthreads();
    }

    // ---- Store: warp w's 16x16 tile -> g_partial[nblk][b0+w*16 ..][u]. ----
    float* op = g_partial + ((size_t)blockIdx.x * BATCH + b0 + w * 16) * UNITS;
    wmma::store_matrix_sync(op, cfrag, UNITS, wmma::mem_row_major);
}

// ---------------------------------------------------------------------------
// Kernel 5: reduce n-block partials, mean over trees.
// ---------------------------------------------------------------------------
__global__ void reduce_kernel(float* __restrict__ out) {
    int i = blockIdx.x * blockDim.x + threadIdx.x;
    float acc = 0.f;
#pragma unroll 8
    for (int nb = 0; nb < NBLK; nb++)
        acc += g_partial[(size_t)nb * BATCH * UNITS + i];
    out[i] = acc * (1.f / (float)NTREES);
}

// ---------------------------------------------------------------------------
extern "C" void kernel_launch(void* const* d_in, const int* in_sizes, int n_in,
                              void* d_out, int out_size) {
    const float* x    = (const float*)d_in[0];   // (1024, 256)
    const float* fsl  = (const float*)d_in[1];   // (256, 512, 6)
    const float* th   = (const float*)d_in[2];   // (512, 6)
    const float* lt   = (const float*)d_in[3];   // (512, 6)
    const float* resp = (const float*)d_in[4];   // (512, 16, 64)
    float* out = (float*)d_out;                  // (1024, 16)

    cudaFuncSetAttribute(resp_mma_kernel,
                         cudaFuncAttributeMaxDynamicSharedMemorySize, RSMEM);

    sparsemax6_kernel<<<(DIM * NTREES + 255) / 256, 256>>>(fsl);
    splitx_kernel<<<(BATCH * DIM + 255) / 256, 256>>>(x);
    fv_mma_kernel<<<dim3(NJ / GN, BATCH / GM), 256, S_TOT>>>(th, lt);
    resp_mma_kernel<<<dim3(NBLK, BBLK), 256, RSMEM>>>(resp);
    reduce_kernel<<<BATCH * UNITS / 256, 256>>>(out);
}

// round 6
// speedup vs baseline: 1.6720x; 1.2301x over previous
#include <cuda_runtime.h>
#include <cuda_fp16.h>
#include <mma.h>
#include <cstdint>

using namespace nvcuda;

// ---------------- problem dims ----------------
#define DIM     256
#define NTREES  512
#define TDEPTH  6
#define UNITS   16
#define LEAVES  64
#define BATCH   1024
#define NJ      (NTREES * TDEPTH)       // 3072 columns (j = n*6+d)

// ---------------- device scratch ----------------
__device__ __align__(16) __half g_xhi[BATCH * DIM];
__device__ __align__(16) __half g_xlo[BATCH * DIM];
__device__ __align__(16) __half g_shi[DIM * NJ];
__device__ __align__(16) __half g_slo[DIM * NJ];
__device__ __align__(16) float  g_fvT[(size_t)NJ * BATCH];   // 12.5 MB, [j][b]
__device__ float g_partial[64 * BATCH * UNITS];              // 4 MB

__device__ __forceinline__ uint32_t h2u(__half2 h) {
    return *reinterpret_cast<uint32_t*>(&h);
}

// ---------------------------------------------------------------------------
// Kernel 1: sparsemax over last axis (6), emitting fp16 hi/lo selector splits
// in [k][j] layout (j = n*6+d).
// ---------------------------------------------------------------------------
__global__ void sparsemax6_kernel(const float* __restrict__ fsl) {
    int row = blockIdx.x * blockDim.x + threadIdx.x;    // row = i*512 + n
    if (row >= DIM * NTREES) return;
    const float* zp = fsl + (size_t)row * TDEPTH;
    float v[TDEPTH], s[TDEPTH];
#pragma unroll
    for (int j = 0; j < TDEPTH; j++) { v[j] = zp[j]; s[j] = v[j]; }
#pragma unroll
    for (int a = 0; a < TDEPTH - 1; a++)
#pragma unroll
        for (int b = 0; b < TDEPTH - 1 - a; b++)
            if (s[b] < s[b + 1]) { float t = s[b]; s[b] = s[b + 1]; s[b + 1] = t; }
    float cs[TDEPTH], acc = 0.f; int cnt = 0;
#pragma unroll
    for (int j = 0; j < TDEPTH; j++) {
        acc += s[j]; cs[j] = acc;
        if (s[j] * (float)(j + 1) > acc - 1.f) cnt++;
    }
    float csk = cs[0];
#pragma unroll
    for (int j = 1; j < TDEPTH; j++) if (cnt == j + 1) csk = cs[j];
    float tau = (csk - 1.f) / (float)cnt;

    int i = row >> 9, n = row & 511;
    size_t base = (size_t)i * NJ + (size_t)n * TDEPTH;
#pragma unroll
    for (int j = 0; j < TDEPTH; j++) {
        float sv = fmaxf(v[j] - tau, 0.f);
        __half hi = __float2half_rn(sv);
        g_shi[base + j] = hi;
        g_slo[base + j] = __float2half_rn(sv - __half2float(hi));
    }
}

// ---------------------------------------------------------------------------
// Kernel 2: split x into fp16 hi/lo.
// ---------------------------------------------------------------------------
__global__ void splitx_kernel(const float* __restrict__ x) {
    int i = blockIdx.x * blockDim.x + threadIdx.x;
    if (i >= BATCH * DIM) return;
    float v = x[i];
    __half hi = __float2half_rn(v);
    g_xhi[i] = hi;
    g_xlo[i] = __float2half_rn(v - __half2float(hi));
}

// ---------------------------------------------------------------------------
// Kernel 3: fv GEMM via wmma (fp16 3-term split, fp32 accum).
// Double-buffered smem, register prefetch, 1 sync/iter. Fragments stored
// DIRECTLY to g_fvT[j][b] (col_major, ldm=BATCH) — no smem epilogue.
// Block: 256 thr = 8 warps (4 M x 2 N), tile M=128(batch) x N=64(j).
// ---------------------------------------------------------------------------
#define GM 128
#define GN 64
#define GK 64
#define A_LDM 72                         // halves, 144 B rows
#define AB_BUF (GM * A_LDM)              // 9216 halves = 18432 B
#define BB_BUF (GK * A_LDM)              // 4608 halves =  9216 B
#define S_TOT  ((AB_BUF + BB_BUF) * 2 * 2)   // 55296 B

__global__ __launch_bounds__(256, 2)
void fv_mma_kernel() {
    extern __shared__ __half smh[];
    __half* As[2] = { smh, smh + AB_BUF };
    __half* Bs[2] = { smh + 2 * AB_BUF, smh + 2 * AB_BUF + BB_BUF };

    const int tid = threadIdx.x;
    const int w   = tid >> 5;
    const int wm  = w & 3;
    const int wn  = w >> 2;
    const int j0  = blockIdx.x * GN;
    const int b0  = blockIdx.y * GM;

    const __half* xs_tab[3] = { g_xhi, g_xlo, g_xhi };
    const __half* ss_tab[3] = { g_shi, g_shi, g_slo };

    // per-thread staging indices (fixed across iters)
    const int ar[4] = { (tid) >> 3, (tid + 256) >> 3, (tid + 512) >> 3, (tid + 768) >> 3 };
    const int ac    = (tid & 7) * 8;
    const int br[2] = { (tid) >> 3, (tid + 256) >> 3 };

    float4 pa[4], pb[2];
    auto ldg_iter = [&](int it) {
        const __half* xs = xs_tab[it >> 2];
        const __half* ss = ss_tab[it >> 2];
        const int k0 = (it & 3) * GK;
#pragma unroll
        for (int q = 0; q < 4; q++)
            pa[q] = *(const float4*)(xs + (size_t)(b0 + ar[q]) * DIM + k0 + ac);
#pragma unroll
        for (int q = 0; q < 2; q++)
            pb[q] = *(const float4*)(ss + (size_t)(k0 + br[q]) * NJ + j0 + ac);
    };
    auto sts_iter = [&](int buf) {
#pragma unroll
        for (int q = 0; q < 4; q++)
            *(float4*)(As[buf] + ar[q] * A_LDM + ac) = pa[q];
#pragma unroll
        for (int q = 0; q < 2; q++)
            *(float4*)(Bs[buf] + br[q] * A_LDM + ac) = pb[q];
    };

    wmma::fragment<wmma::accumulator, 16, 16, 16, float> c[2][2];
#pragma unroll
    for (int i = 0; i < 2; i++)
#pragma unroll
        for (int j = 0; j < 2; j++) wmma::fill_fragment(c[i][j], 0.f);

    ldg_iter(0);
    sts_iter(0);
    __syncthreads();

#pragma unroll 1
    for (int it = 0; it < 12; it++) {
        const int buf = it & 1;
        if (it < 11) ldg_iter(it + 1);
#pragma unroll
        for (int kk = 0; kk < GK / 16; kk++) {
            wmma::fragment<wmma::matrix_a, 16, 16, 16, __half, wmma::row_major> a[2];
            wmma::fragment<wmma::matrix_b, 16, 16, 16, __half, wmma::row_major> b[2];
#pragma unroll
            for (int i = 0; i < 2; i++)
                wmma::load_matrix_sync(a[i], As[buf] + (wm * 32 + i * 16) * A_LDM + kk * 16, A_LDM);
#pragma unroll
            for (int j = 0; j < 2; j++)
                wmma::load_matrix_sync(b[j], Bs[buf] + (kk * 16) * A_LDM + wn * 32 + j * 16, A_LDM);
#pragma unroll
            for (int i = 0; i < 2; i++)
#pragma unroll
                for (int j = 0; j < 2; j++)
                    wmma::mma_sync(c[i][j], a[i], b[j], c[i][j]);
        }
        if (it < 11) {
            sts_iter(buf ^ 1);
            __syncthreads();
        }
    }

    // Direct store: fvT[j][b] = col_major tile (row = b, col = j), ldm = BATCH.
#pragma unroll
    for (int i = 0; i < 2; i++)
#pragma unroll
        for (int j = 0; j < 2; j++)
            wmma::store_matrix_sync(
                g_fvT + (size_t)(j0 + wn * 32 + j * 16) * BATCH + b0 + wm * 32 + i * 16,
                c[i][j], BATCH, wmma::mem_col_major);
}

// ---------------------------------------------------------------------------
// Kernel 4: response contraction via wmma — warp-private W tiles, NO block
// barriers in the tree loop. Warp w builds and consumes W rows [w*16, w*16+16).
// Gates computed inline from g_fvT (th/ein staged in smem).
// ---------------------------------------------------------------------------
#define BT    128
#define NT    8
#define NBLK  (NTREES / NT)             // 64
#define BBLK  (BATCH / BT)              // 8
#define W_LDM 72
#define R_LDM 72

#define RS_WHI 0                        // 128*72*2 = 18432
#define RS_WLO 18432
#define RS_RHI 36864                    // 8*16*72*2 = 18432
#define RS_RLO 55296
#define RS_TH  73728                    // 48 floats
#define RS_EI  (73728 + 192)            // 48 floats
#define RSMEM  (73728 + 384)

__global__ __launch_bounds__(256, 2)
void resp_mma_kernel(const float* __restrict__ resp,
                     const float* __restrict__ th,
                     const float* __restrict__ lt) {
    extern __shared__ char smem[];
    __half* Whi_s = (__half*)(smem + RS_WHI);
    __half* Wlo_s = (__half*)(smem + RS_WLO);
    __half* rhi_s = (__half*)(smem + RS_RHI);
    __half* rlo_s = (__half*)(smem + RS_RLO);
    float*  th_s  = (float*)(smem + RS_TH);
    float*  ei_s  = (float*)(smem + RS_EI);

    const int tid = threadIdx.x;
    const int w   = tid >> 5;
    const int l   = tid & 31;
    const int n0  = blockIdx.x * NT;
    const int b0  = blockIdx.y * BT;

    // Stage response (8 trees x 16 u x 64 c) as fp16 hi/lo, ldm=72.
    for (int i = tid; i < NT * UNITS * LEAVES; i += 256) {
        int t = i >> 10, rem = i & 1023;          // rem = u*64 + c
        int u = rem >> 6, c = rem & 63;
        float v = resp[(size_t)(n0 + t) * (UNITS * LEAVES) + rem];
        __half hi = __float2half_rn(v);
        rhi_s[(t * UNITS + u) * R_LDM + c] = hi;
        rlo_s[(t * UNITS + u) * R_LDM + c] = __float2half_rn(v - __half2float(hi));
    }
    if (tid < NT * TDEPTH) {
        th_s[tid] = th[n0 * TDEPTH + tid];
        ei_s[tid] = __expf(-lt[n0 * TDEPTH + tid]);
    }

    wmma::fragment<wmma::accumulator, 16, 16, 16, float> cfrag;
    wmma::fill_fragment(cfrag, 0.f);
    __syncthreads();

    // Warp-private W build: lane covers row w*16 + (l&15), leaves [32h, 32h+32).
    const int rl = l & 15;              // local row within warp tile
    const int h  = l >> 4;              // leaf half
    const int bg = b0 + w * 16 + rl;    // global batch row

    float fvv[TDEPTH];
#pragma unroll
    for (int d = 0; d < TDEPTH; d++)
        fvv[d] = g_fvT[(size_t)(n0 * TDEPTH + d) * BATCH + bg];

#pragma unroll 1
    for (int t = 0; t < NT; t++) {
        __syncwarp();                   // MMA reads of prev W done (cross-lane)
        // ---- gates + leaf weights for tree n0+t ----
        {
            float gp[TDEPTH], gn[TDEPTH];
#pragma unroll
            for (int d = 0; d < TDEPTH; d++) {
                float tt = (fvv[d] - th_s[t * TDEPTH + d]) * ei_s[t * TDEPTH + d];
                gp[d] = __saturatef(fmaf(0.5f, tt, 0.5f));
                gn[d] = 1.f - gp[d];
            }
            float wlo[4];
            wlo[0] = gp[0] * gp[1];
            wlo[1] = gn[0] * gp[1];
            wlo[2] = gp[0] * gn[1];
            wlo[3] = gn[0] * gn[1];
            float g5 = h ? gn[5] : gp[5];
            float a3[4], whi8[8];
            a3[0] = gp[2] * gp[3]; a3[1] = gn[2] * gp[3];
            a3[2] = gp[2] * gn[3]; a3[3] = gn[2] * gn[3];
#pragma unroll
            for (int j = 0; j < 4; j++) {
                whi8[j]     = a3[j] * gp[4] * g5;
                whi8[j + 4] = a3[j] * gn[4] * g5;
            }

            uint32_t uhi[16], ulo[16];
#pragma unroll
            for (int j = 0; j < 8; j++) {
                float w0 = wlo[0] * whi8[j], w1 = wlo[1] * whi8[j];
                float w2 = wlo[2] * whi8[j], w3 = wlo[3] * whi8[j];
                __half2 h01 = __floats2half2_rn(w0, w1);
                __half2 h23 = __floats2half2_rn(w2, w3);
                __half2 l01 = __floats2half2_rn(w0 - __low2float(h01),
                                                w1 - __high2float(h01));
                __half2 l23 = __floats2half2_rn(w2 - __low2float(h23),
                                                w3 - __high2float(h23));
                uhi[j * 2] = h2u(h01); uhi[j * 2 + 1] = h2u(h23);
                ulo[j * 2] = h2u(l01); ulo[j * 2 + 1] = h2u(l23);
            }
            uint4* dh = (uint4*)(Whi_s + (w * 16 + rl) * W_LDM + h * 32);
            uint4* dl = (uint4*)(Wlo_s + (w * 16 + rl) * W_LDM + h * 32);
#pragma unroll
            for (int q = 0; q < 4; q++) {
                dh[q] = make_uint4(uhi[q * 4], uhi[q * 4 + 1], uhi[q * 4 + 2], uhi[q * 4 + 3]);
                dl[q] = make_uint4(ulo[q * 4], ulo[q * 4 + 1], ulo[q * 4 + 2], ulo[q * 4 + 3]);
            }
        }
        __syncwarp();                   // W writes visible warp-wide

        // prefetch next tree's fv (overlaps MMA section)
        if (t < NT - 1) {
#pragma unroll
            for (int d = 0; d < TDEPTH; d++)
                fvv[d] = g_fvT[(size_t)((n0 + t + 1) * TDEPTH + d) * BATCH + bg];
        }

        // ---- MMA: out += Whi@Rhi + Wlo@Rhi + Whi@Rlo ----
        const __half* rh = rhi_s + t * UNITS * R_LDM;
        const __half* rl2 = rlo_s + t * UNITS * R_LDM;
#pragma unroll
        for (int kk = 0; kk < LEAVES / 16; kk++) {
            wmma::fragment<wmma::matrix_a, 16, 16, 16, __half, wmma::row_major> ahi, alo;
            wmma::fragment<wmma::matrix_b, 16, 16, 16, __half, wmma::col_major> bhi, blo;
            wmma::load_matrix_sync(ahi, Whi_s + (w * 16) * W_LDM + kk * 16, W_LDM);
            wmma::load_matrix_sync(alo, Wlo_s + (w * 16) * W_LDM + kk * 16, W_LDM);
            wmma::load_matrix_sync(bhi, rh + kk * 16, R_LDM);
            wmma::load_matrix_sync(blo, rl2 + kk * 16, R_LDM);
            wmma::mma_sync(cfrag, ahi, bhi, cfrag);
            wmma::mma_sync(cfrag, alo, bhi, cfrag);
            wmma::mma_sync(cfrag, ahi, blo, cfrag);
        }
    }

    float* op = g_partial + ((size_t)blockIdx.x * BATCH + b0 + w * 16) * UNITS;
    wmma::store_matrix_sync(op, cfrag, UNITS, wmma::mem_row_major);
}

// ---------------------------------------------------------------------------
// Kernel 5: reduce n-block partials, mean over trees.
// ---------------------------------------------------------------------------
__global__ void reduce_kernel(float* __restrict__ out) {
    int i = blockIdx.x * blockDim.x + threadIdx.x;
    float acc = 0.f;
#pragma unroll 8
    for (int nb = 0; nb < NBLK; nb++)
        acc += g_partial[(size_t)nb * BATCH * UNITS + i];
    out[i] = acc * (1.f / (float)NTREES);
}

// ---------------------------------------------------------------------------
extern "C" void kernel_launch(void* const* d_in, const int* in_sizes, int n_in,
                              void* d_out, int out_size) {
    const float* x    = (const float*)d_in[0];   // (1024, 256)
    const float* fsl  = (const float*)d_in[1];   // (256, 512, 6)
    const float* th   = (const float*)d_in[2];   // (512, 6)
    const float* lt   = (const float*)d_in[3];   // (512, 6)
    const float* resp = (const float*)d_in[4];   // (512, 16, 64)
    float* out = (float*)d_out;                  // (1024, 16)

    cudaFuncSetAttribute(fv_mma_kernel,
                         cudaFuncAttributeMaxDynamicSharedMemorySize, S_TOT);
    cudaFuncSetAttribute(resp_mma_kernel,
                         cudaFuncAttributeMaxDynamicSharedMemorySize, RSMEM);

    sparsemax6_kernel<<<(DIM * NTREES + 255) / 256, 256>>>(fsl);
    splitx_kernel<<<(BATCH * DIM + 255) / 256, 256>>>(x);
    fv_mma_kernel<<<dim3(NJ / GN, BATCH / GM), 256, S_TOT>>>();
    resp_mma_kernel<<<dim3(NBLK, BBLK), 256, RSMEM>>>(resp, th, lt);
    reduce_kernel<<<BATCH * UNITS / 256, 256>>>(out);
}

// round 7
// speedup vs baseline: 1.7751x; 1.0616x over previous
#include <cuda_runtime.h>
#include <cuda_fp16.h>
#include <mma.h>
#include <cstdint>

using namespace nvcuda;

// ---------------- problem dims ----------------
#define DIM     256
#define NTREES  512
#define TDEPTH  6
#define UNITS   16
#define LEAVES  64
#define BATCH   1024
#define NJ      (NTREES * TDEPTH)       // 3072 columns (j = n*6+d)

// ---------------- device scratch ----------------
__device__ __align__(16) __half g_xhi[BATCH * DIM];
__device__ __align__(16) __half g_xlo[BATCH * DIM];
__device__ __align__(16) __half g_shi[DIM * NJ];
__device__ __align__(16) __half g_slo[DIM * NJ];
__device__ __align__(16) float  g_fvT[(size_t)NJ * BATCH];   // 12.5 MB, [j][b]
__device__ float g_partial[128 * BATCH * UNITS];             // 8 MB

__device__ __forceinline__ uint32_t h2u(__half2 h) {
    return *reinterpret_cast<uint32_t*>(&h);
}
__device__ __forceinline__ uint32_t smem_u32(const void* p) {
    uint32_t a;
    asm("{ .reg .u64 t; cvta.to.shared.u64 t, %1; cvt.u32.u64 %0, t; }" : "=r"(a) : "l"(p));
    return a;
}
__device__ __forceinline__ void cp_async16(uint32_t dst, const void* src) {
    asm volatile("cp.async.cg.shared.global [%0], [%1], 16;" :: "r"(dst), "l"(src));
}
#define CP_COMMIT()  asm volatile("cp.async.commit_group;" ::: "memory")
#define CP_WAIT(n)   asm volatile("cp.async.wait_group %0;" :: "n"(n) : "memory")

// ---------------------------------------------------------------------------
// Kernel 1: fused prep — sparsemax (blocks [0,512)) + x split (blocks [512,1536)).
// ---------------------------------------------------------------------------
__global__ void prep_kernel(const float* __restrict__ fsl,
                            const float* __restrict__ x) {
    if (blockIdx.x < 512) {
        int row = blockIdx.x * blockDim.x + threadIdx.x;    // row = i*512 + n
        const float* zp = fsl + (size_t)row * TDEPTH;
        float v[TDEPTH], s[TDEPTH];
#pragma unroll
        for (int j = 0; j < TDEPTH; j++) { v[j] = zp[j]; s[j] = v[j]; }
#pragma unroll
        for (int a = 0; a < TDEPTH - 1; a++)
#pragma unroll
            for (int b = 0; b < TDEPTH - 1 - a; b++)
                if (s[b] < s[b + 1]) { float t = s[b]; s[b] = s[b + 1]; s[b + 1] = t; }
        float cs[TDEPTH], acc = 0.f; int cnt = 0;
#pragma unroll
        for (int j = 0; j < TDEPTH; j++) {
            acc += s[j]; cs[j] = acc;
            if (s[j] * (float)(j + 1) > acc - 1.f) cnt++;
        }
        float csk = cs[0];
#pragma unroll
        for (int j = 1; j < TDEPTH; j++) if (cnt == j + 1) csk = cs[j];
        float tau = (csk - 1.f) / (float)cnt;

        int i = row >> 9, n = row & 511;
        size_t base = (size_t)i * NJ + (size_t)n * TDEPTH;
#pragma unroll
        for (int j = 0; j < TDEPTH; j++) {
            float sv = fmaxf(v[j] - tau, 0.f);
            __half hi = __float2half_rn(sv);
            g_shi[base + j] = hi;
            g_slo[base + j] = __float2half_rn(sv - __half2float(hi));
        }
    } else {
        int i = (blockIdx.x - 512) * blockDim.x + threadIdx.x;
        float v = x[i];
        __half hi = __float2half_rn(v);
        g_xhi[i] = hi;
        g_xlo[i] = __float2half_rn(v - __half2float(hi));
    }
}

// ---------------------------------------------------------------------------
// Kernel 2: fv GEMM via wmma (fp16 3-term split, fp32 accum).
// GK=128, cp.async double-buffered staging (6 iterations), direct col_major
// fragment store to g_fvT[j][b].
// ---------------------------------------------------------------------------
#define GM 128
#define GN 64
#define GK 128
#define A_LDM 136                        // halves (272 B rows, 16B-mult)
#define B_LDM 72                         // halves (144 B rows)
#define A_BUF (GM * A_LDM)               // 17408 halves
#define B_BUF (GK * B_LDM)               // 9216 halves
#define S_TOT ((A_BUF + B_BUF) * 2 * 2)  // 106496 B

__global__ __launch_bounds__(256, 2)
void fv_mma_kernel() {
    extern __shared__ __half smh[];
    __half* As[2] = { smh, smh + A_BUF };
    __half* Bs[2] = { smh + 2 * A_BUF, smh + 2 * A_BUF + B_BUF };
    const uint32_t sbase = smem_u32(smh);

    const int tid = threadIdx.x;
    const int w   = tid >> 5;
    const int wm  = w & 3;
    const int wn  = w >> 2;
    const int j0  = blockIdx.x * GN;
    const int b0  = blockIdx.y * GM;

    // cp.async staging: A = 2048 16B-chunks (8/thr), B = 1024 (4/thr).
    auto stage = [&](int it, int buf) {
        const int seg = it >> 1;
        const __half* xs = (seg == 1) ? g_xlo : g_xhi;
        const __half* ss = (seg == 2) ? g_slo : g_shi;
        const int k0 = (it & 1) * GK;
        const uint32_t adst = sbase + (uint32_t)(buf ? A_BUF : 0) * 2;
        const uint32_t bdst = sbase + (uint32_t)(2 * A_BUF + (buf ? B_BUF : 0)) * 2;
#pragma unroll
        for (int q = 0; q < 8; q++) {
            int id  = tid + q * 256;
            int row = id >> 4, c16 = id & 15;        // 16 chunks per 256B row
            cp_async16(adst + (uint32_t)row * (A_LDM * 2) + c16 * 16,
                       xs + (size_t)(b0 + row) * DIM + k0 + c16 * 8);
        }
#pragma unroll
        for (int q = 0; q < 4; q++) {
            int id  = tid + q * 256;
            int row = id >> 3, c16 = id & 7;         // 8 chunks per 128B row
            cp_async16(bdst + (uint32_t)row * (B_LDM * 2) + c16 * 16,
                       ss + (size_t)(k0 + row) * NJ + j0 + c16 * 8);
        }
        CP_COMMIT();
    };

    wmma::fragment<wmma::accumulator, 16, 16, 16, float> c[2][2];
#pragma unroll
    for (int i = 0; i < 2; i++)
#pragma unroll
        for (int j = 0; j < 2; j++) wmma::fill_fragment(c[i][j], 0.f);

    stage(0, 0);

#pragma unroll 1
    for (int it = 0; it < 6; it++) {
        const int buf = it & 1;
        if (it < 5) stage(it + 1, buf ^ 1);
        if (it < 5) { CP_WAIT(1); } else { CP_WAIT(0); }
        __syncthreads();

#pragma unroll
        for (int kk = 0; kk < GK / 16; kk++) {
            wmma::fragment<wmma::matrix_a, 16, 16, 16, __half, wmma::row_major> a[2];
            wmma::fragment<wmma::matrix_b, 16, 16, 16, __half, wmma::row_major> b[2];
#pragma unroll
            for (int i = 0; i < 2; i++)
                wmma::load_matrix_sync(a[i], As[buf] + (wm * 32 + i * 16) * A_LDM + kk * 16, A_LDM);
#pragma unroll
            for (int j = 0; j < 2; j++)
                wmma::load_matrix_sync(b[j], Bs[buf] + (kk * 16) * B_LDM + wn * 32 + j * 16, B_LDM);
#pragma unroll
            for (int i = 0; i < 2; i++)
#pragma unroll
                for (int j = 0; j < 2; j++)
                    wmma::mma_sync(c[i][j], a[i], b[j], c[i][j]);
        }
        __syncthreads();   // all warps done reading buf before it's re-filled
    }

    // Direct store: fvT[j][b] (col_major tile, ldm = BATCH).
#pragma unroll
    for (int i = 0; i < 2; i++)
#pragma unroll
        for (int j = 0; j < 2; j++)
            wmma::store_matrix_sync(
                g_fvT + (size_t)(j0 + wn * 32 + j * 16) * BATCH + b0 + wm * 32 + i * 16,
                c[i][j], BATCH, wmma::mem_col_major);
}

// ---------------------------------------------------------------------------
// Kernel 3: response contraction via wmma — warp-private W tiles, no block
// barriers in tree loop. NT=4 trees/block -> 55.5 KB smem -> 3 CTAs/SM.
// ---------------------------------------------------------------------------
#define BT    128
#define NT    4
#define NBLK  (NTREES / NT)             // 128
#define W_LDM 72
#define R_LDM 72

#define RS_WHI 0                        // 128*72*2 = 18432
#define RS_WLO 18432
#define RS_RHI 36864                    // 4*16*72*2 = 9216
#define RS_RLO 46080
#define RS_TH  55296                    // 24 floats (pad 128)
#define RS_EI  (55296 + 128)
#define RSMEM  (55296 + 256)

__global__ __launch_bounds__(256, 3)
void resp_mma_kernel(const float* __restrict__ resp,
                     const float* __restrict__ th,
                     const float* __restrict__ lt) {
    extern __shared__ char smem[];
    __half* Whi_s = (__half*)(smem + RS_WHI);
    __half* Wlo_s = (__half*)(smem + RS_WLO);
    __half* rhi_s = (__half*)(smem + RS_RHI);
    __half* rlo_s = (__half*)(smem + RS_RLO);
    float*  th_s  = (float*)(smem + RS_TH);
    float*  ei_s  = (float*)(smem + RS_EI);

    const int tid = threadIdx.x;
    const int w   = tid >> 5;
    const int l   = tid & 31;
    const int n0  = blockIdx.x * NT;
    const int b0  = blockIdx.y * BT;

    // Stage response (4 trees x 16 u x 64 c) as fp16 hi/lo, half2-vectorized.
    for (int i = tid; i < NT * UNITS * LEAVES / 2; i += 256) {
        int t = i >> 9, rem2 = i & 511;           // rem2 = u*32 + c2
        int u = rem2 >> 5, c2 = rem2 & 31;
        float2 v = *(const float2*)(resp + (size_t)(n0 + t) * (UNITS * LEAVES) + u * 64 + c2 * 2);
        __half2 hi = __floats2half2_rn(v.x, v.y);
        __half2 lo = __floats2half2_rn(v.x - __low2float(hi), v.y - __high2float(hi));
        *(__half2*)(rhi_s + (t * UNITS + u) * R_LDM + c2 * 2) = hi;
        *(__half2*)(rlo_s + (t * UNITS + u) * R_LDM + c2 * 2) = lo;
    }
    if (tid < NT * TDEPTH) {
        th_s[tid] = th[n0 * TDEPTH + tid];
        ei_s[tid] = __expf(-lt[n0 * TDEPTH + tid]);
    }

    wmma::fragment<wmma::accumulator, 16, 16, 16, float> cfrag;
    wmma::fill_fragment(cfrag, 0.f);
    __syncthreads();

    const int rl = l & 15;              // local row within warp tile
    const int h  = l >> 4;              // leaf half
    const int bg = b0 + w * 16 + rl;    // global batch row

    float fvv[TDEPTH];
#pragma unroll
    for (int d = 0; d < TDEPTH; d++)
        fvv[d] = g_fvT[(size_t)(n0 * TDEPTH + d) * BATCH + bg];

#pragma unroll 1
    for (int t = 0; t < NT; t++) {
        __syncwarp();
        // ---- gates + leaf weights for tree n0+t ----
        {
            float gp[TDEPTH], gn[TDEPTH];
#pragma unroll
            for (int d = 0; d < TDEPTH; d++) {
                float tt = (fvv[d] - th_s[t * TDEPTH + d]) * ei_s[t * TDEPTH + d];
                gp[d] = __saturatef(fmaf(0.5f, tt, 0.5f));
                gn[d] = 1.f - gp[d];
            }
            float wlo[4];
            wlo[0] = gp[0] * gp[1];
            wlo[1] = gn[0] * gp[1];
            wlo[2] = gp[0] * gn[1];
            wlo[3] = gn[0] * gn[1];
            float g5 = h ? gn[5] : gp[5];
            float a3[4], whi8[8];
            a3[0] = gp[2] * gp[3]; a3[1] = gn[2] * gp[3];
            a3[2] = gp[2] * gn[3]; a3[3] = gn[2] * gn[3];
#pragma unroll
            for (int j = 0; j < 4; j++) {
                whi8[j]     = a3[j] * gp[4] * g5;
                whi8[j + 4] = a3[j] * gn[4] * g5;
            }

            uint32_t uhi[16], ulo[16];
#pragma unroll
            for (int j = 0; j < 8; j++) {
                float w0 = wlo[0] * whi8[j], w1 = wlo[1] * whi8[j];
                float w2 = wlo[2] * whi8[j], w3 = wlo[3] * whi8[j];
                __half2 h01 = __floats2half2_rn(w0, w1);
                __half2 h23 = __floats2half2_rn(w2, w3);
                __half2 l01 = __floats2half2_rn(w0 - __low2float(h01),
                                                w1 - __high2float(h01));
                __half2 l23 = __floats2half2_rn(w2 - __low2float(h23),
                                                w3 - __high2float(h23));
                uhi[j * 2] = h2u(h01); uhi[j * 2 + 1] = h2u(h23);
                ulo[j * 2] = h2u(l01); ulo[j * 2 + 1] = h2u(l23);
            }
            uint4* dh = (uint4*)(Whi_s + (w * 16 + rl) * W_LDM + h * 32);
            uint4* dl = (uint4*)(Wlo_s + (w * 16 + rl) * W_LDM + h * 32);
#pragma unroll
            for (int q = 0; q < 4; q++) {
                dh[q] = make_uint4(uhi[q * 4], uhi[q * 4 + 1], uhi[q * 4 + 2], uhi[q * 4 + 3]);
                dl[q] = make_uint4(ulo[q * 4], ulo[q * 4 + 1], ulo[q * 4 + 2], ulo[q * 4 + 3]);
            }
        }
        __syncwarp();

        if (t < NT - 1) {
#pragma unroll
            for (int d = 0; d < TDEPTH; d++)
                fvv[d] = g_fvT[(size_t)((n0 + t + 1) * TDEPTH + d) * BATCH + bg];
        }

        // ---- MMA: out += Whi@Rhi + Wlo@Rhi + Whi@Rlo ----
        const __half* rh  = rhi_s + t * UNITS * R_LDM;
        const __half* rl2 = rlo_s + t * UNITS * R_LDM;
#pragma unroll
        for (int kk = 0; kk < LEAVES / 16; kk++) {
            wmma::fragment<wmma::matrix_a, 16, 16, 16, __half, wmma::row_major> ahi, alo;
            wmma::fragment<wmma::matrix_b, 16, 16, 16, __half, wmma::col_major> bhi, blo;
            wmma::load_matrix_sync(ahi, Whi_s + (w * 16) * W_LDM + kk * 16, W_LDM);
            wmma::load_matrix_sync(alo, Wlo_s + (w * 16) * W_LDM + kk * 16, W_LDM);
            wmma::load_matrix_sync(bhi, rh + kk * 16, R_LDM);
            wmma::load_matrix_sync(blo, rl2 + kk * 16, R_LDM);
            wmma::mma_sync(cfrag, ahi, bhi, cfrag);
            wmma::mma_sync(cfrag, alo, bhi, cfrag);
            wmma::mma_sync(cfrag, ahi, blo, cfrag);
        }
    }

    float* op = g_partial + ((size_t)blockIdx.x * BATCH + b0 + w * 16) * UNITS;
    wmma::store_matrix_sync(op, cfrag, UNITS, wmma::mem_row_major);
}

// ---------------------------------------------------------------------------
// Kernel 4: reduce n-block partials, mean over trees.
// ---------------------------------------------------------------------------
__global__ void reduce_kernel(float* __restrict__ out) {
    int i = blockIdx.x * blockDim.x + threadIdx.x;
    float acc = 0.f;
#pragma unroll 8
    for (int nb = 0; nb < NBLK; nb++)
        acc += g_partial[(size_t)nb * BATCH * UNITS + i];
    out[i] = acc * (1.f / (float)NTREES);
}

// ---------------------------------------------------------------------------
extern "C" void kernel_launch(void* const* d_in, const int* in_sizes, int n_in,
                              void* d_out, int out_size) {
    const float* x    = (const float*)d_in[0];   // (1024, 256)
    const float* fsl  = (const float*)d_in[1];   // (256, 512, 6)
    const float* th   = (const float*)d_in[2];   // (512, 6)
    const float* lt   = (const float*)d_in[3];   // (512, 6)
    const float* resp = (const float*)d_in[4];   // (512, 16, 64)
    float* out = (float*)d_out;                  // (1024, 16)

    cudaFuncSetAttribute(fv_mma_kernel,
                         cudaFuncAttributeMaxDynamicSharedMemorySize, S_TOT);
    cudaFuncSetAttribute(resp_mma_kernel,
                         cudaFuncAttributeMaxDynamicSharedMemorySize, RSMEM);

    prep_kernel<<<1536, 256>>>(fsl, x);
    fv_mma_kernel<<<dim3(NJ / GN, BATCH / GM), 256, S_TOT>>>();
    resp_mma_kernel<<<dim3(NBLK, BATCH / BT), 256, RSMEM>>>(resp, th, lt);
    reduce_kernel<<<BATCH * UNITS / 256, 256>>>(out);
}

// round 8
// speedup vs baseline: 1.8320x; 1.0321x over previous
#include <cuda_runtime.h>
#include <cuda_fp16.h>
#include <mma.h>
#include <cstdint>

using namespace nvcuda;

// ---------------- problem dims ----------------
#define DIM     256
#define NTREES  512
#define TDEPTH  6
#define UNITS   16
#define LEAVES  64
#define BATCH   1024
#define NJ      (NTREES * TDEPTH)       // 3072 columns (j = n*6+d)

// ---------------- device scratch ----------------
__device__ __align__(16) __half g_xhi[BATCH * DIM];
__device__ __align__(16) __half g_xlo[BATCH * DIM];
__device__ __align__(16) __half g_shi[DIM * NJ];
__device__ __align__(16) __half g_slo[DIM * NJ];
__device__ __align__(16) float  g_fvT[(size_t)NJ * BATCH];   // 12.5 MB, [j][b]
__device__ float g_partial[128 * BATCH * UNITS];             // 8 MB
__device__ float g_red[8 * BATCH * UNITS];                   // 512 KB

__device__ __forceinline__ uint32_t h2u(__half2 h) {
    return *reinterpret_cast<uint32_t*>(&h);
}
__device__ __forceinline__ uint32_t smem_u32(const void* p) {
    uint32_t a;
    asm("{ .reg .u64 t; cvta.to.shared.u64 t, %1; cvt.u32.u64 %0, t; }" : "=r"(a) : "l"(p));
    return a;
}
__device__ __forceinline__ void cp_async16(uint32_t dst, const void* src) {
    asm volatile("cp.async.cg.shared.global [%0], [%1], 16;" :: "r"(dst), "l"(src));
}
#define CP_COMMIT()  asm volatile("cp.async.commit_group;" ::: "memory")
#define CP_WAIT(n)   asm volatile("cp.async.wait_group %0;" :: "n"(n) : "memory")

// ---------------------------------------------------------------------------
// Kernel 1: fused prep — sparsemax (blocks [0,256), 2 rows/thread, float4
// loads) + x split (blocks [256,512), float4).
// ---------------------------------------------------------------------------
__global__ void prep_kernel(const float* __restrict__ fsl,
                            const float* __restrict__ x) {
    if (blockIdx.x < 256) {
        // Two sparsemax rows per thread: 12 floats = 3 aligned float4.
        int pr = blockIdx.x * blockDim.x + threadIdx.x;     // row pair 0..65535
        const float4* zp4 = (const float4*)(fsl + (size_t)pr * 12);
        float4 q0 = zp4[0], q1 = zp4[1], q2 = zp4[2];
        float vv[12] = { q0.x, q0.y, q0.z, q0.w, q1.x, q1.y,
                         q1.z, q1.w, q2.x, q2.y, q2.z, q2.w };
        __half oh[12], ol[12];
#pragma unroll
        for (int rr = 0; rr < 2; rr++) {
            float* v = vv + rr * 6;
            float s[TDEPTH];
#pragma unroll
            for (int j = 0; j < TDEPTH; j++) s[j] = v[j];
#pragma unroll
            for (int a = 0; a < TDEPTH - 1; a++)
#pragma unroll
                for (int b = 0; b < TDEPTH - 1 - a; b++)
                    if (s[b] < s[b + 1]) { float t = s[b]; s[b] = s[b + 1]; s[b + 1] = t; }
            float cs[TDEPTH], acc = 0.f; int cnt = 0;
#pragma unroll
            for (int j = 0; j < TDEPTH; j++) {
                acc += s[j]; cs[j] = acc;
                if (s[j] * (float)(j + 1) > acc - 1.f) cnt++;
            }
            float csk = cs[0];
#pragma unroll
            for (int j = 1; j < TDEPTH; j++) if (cnt == j + 1) csk = cs[j];
            float tau = (csk - 1.f) / (float)cnt;
#pragma unroll
            for (int j = 0; j < TDEPTH; j++) {
                float sv = fmaxf(v[j] - tau, 0.f);
                __half hi = __float2half_rn(sv);
                oh[rr * 6 + j] = hi;
                ol[rr * 6 + j] = __float2half_rn(sv - __half2float(hi));
            }
        }
        // rows 2pr, 2pr+1 are consecutive in (i, n) order; the [i][j] layout
        // (j = n*6+d) keeps them contiguous: 12 halves = 24 B (8B-aligned).
        size_t base = (size_t)pr * 12;
        uint2* dh = (uint2*)(g_shi + base);
        uint2* dl = (uint2*)(g_slo + base);
        const uint2* sh = (const uint2*)oh;
        const uint2* sl = (const uint2*)ol;
#pragma unroll
        for (int q = 0; q < 3; q++) { dh[q] = sh[q]; dl[q] = sl[q]; }
    } else {
        int i4 = (blockIdx.x - 256) * blockDim.x + threadIdx.x;  // 0..65535
        float4 v = *(const float4*)(x + (size_t)i4 * 4);
        __half2 h01 = __floats2half2_rn(v.x, v.y);
        __half2 h23 = __floats2half2_rn(v.z, v.w);
        __half2 l01 = __floats2half2_rn(v.x - __low2float(h01), v.y - __high2float(h01));
        __half2 l23 = __floats2half2_rn(v.z - __low2float(h23), v.w - __high2float(h23));
        *(uint2*)(g_xhi + (size_t)i4 * 4) = make_uint2(h2u(h01), h2u(h23));
        *(uint2*)(g_xlo + (size_t)i4 * 4) = make_uint2(h2u(l01), h2u(l23));
    }
}

// ---------------------------------------------------------------------------
// Kernel 2: fv GEMM via wmma (fp16 3-term split, fp32 accum).
// GK=128, cp.async double-buffered, direct col_major store to g_fvT[j][b].
// ---------------------------------------------------------------------------
#define GM 128
#define GN 64
#define GK 128
#define A_LDM 136
#define B_LDM 72
#define A_BUF (GM * A_LDM)
#define B_BUF (GK * B_LDM)
#define S_TOT ((A_BUF + B_BUF) * 2 * 2)  // 106496 B

__global__ __launch_bounds__(256, 2)
void fv_mma_kernel() {
    extern __shared__ __half smh[];
    __half* As[2] = { smh, smh + A_BUF };
    __half* Bs[2] = { smh + 2 * A_BUF, smh + 2 * A_BUF + B_BUF };
    const uint32_t sbase = smem_u32(smh);

    const int tid = threadIdx.x;
    const int w   = tid >> 5;
    const int wm  = w & 3;
    const int wn  = w >> 2;
    const int j0  = blockIdx.x * GN;
    const int b0  = blockIdx.y * GM;

    auto stage = [&](int it, int buf) {
        const int seg = it >> 1;
        const __half* xs = (seg == 1) ? g_xlo : g_xhi;
        const __half* ss = (seg == 2) ? g_slo : g_shi;
        const int k0 = (it & 1) * GK;
        const uint32_t adst = sbase + (uint32_t)(buf ? A_BUF : 0) * 2;
        const uint32_t bdst = sbase + (uint32_t)(2 * A_BUF + (buf ? B_BUF : 0)) * 2;
#pragma unroll
        for (int q = 0; q < 8; q++) {
            int id  = tid + q * 256;
            int row = id >> 4, c16 = id & 15;
            cp_async16(adst + (uint32_t)row * (A_LDM * 2) + c16 * 16,
                       xs + (size_t)(b0 + row) * DIM + k0 + c16 * 8);
        }
#pragma unroll
        for (int q = 0; q < 4; q++) {
            int id  = tid + q * 256;
            int row = id >> 3, c16 = id & 7;
            cp_async16(bdst + (uint32_t)row * (B_LDM * 2) + c16 * 16,
                       ss + (size_t)(k0 + row) * NJ + j0 + c16 * 8);
        }
        CP_COMMIT();
    };

    wmma::fragment<wmma::accumulator, 16, 16, 16, float> c[2][2];
#pragma unroll
    for (int i = 0; i < 2; i++)
#pragma unroll
        for (int j = 0; j < 2; j++) wmma::fill_fragment(c[i][j], 0.f);

    stage(0, 0);

#pragma unroll 1
    for (int it = 0; it < 6; it++) {
        const int buf = it & 1;
        if (it < 5) stage(it + 1, buf ^ 1);
        if (it < 5) { CP_WAIT(1); } else { CP_WAIT(0); }
        __syncthreads();

#pragma unroll
        for (int kk = 0; kk < GK / 16; kk++) {
            wmma::fragment<wmma::matrix_a, 16, 16, 16, __half, wmma::row_major> a[2];
            wmma::fragment<wmma::matrix_b, 16, 16, 16, __half, wmma::row_major> b[2];
#pragma unroll
            for (int i = 0; i < 2; i++)
                wmma::load_matrix_sync(a[i], As[buf] + (wm * 32 + i * 16) * A_LDM + kk * 16, A_LDM);
#pragma unroll
            for (int j = 0; j < 2; j++)
                wmma::load_matrix_sync(b[j], Bs[buf] + (kk * 16) * B_LDM + wn * 32 + j * 16, B_LDM);
#pragma unroll
            for (int i = 0; i < 2; i++)
#pragma unroll
                for (int j = 0; j < 2; j++)
                    wmma::mma_sync(c[i][j], a[i], b[j], c[i][j]);
        }
        __syncthreads();
    }

#pragma unroll
    for (int i = 0; i < 2; i++)
#pragma unroll
        for (int j = 0; j < 2; j++)
            wmma::store_matrix_sync(
                g_fvT + (size_t)(j0 + wn * 32 + j * 16) * BATCH + b0 + wm * 32 + i * 16,
                c[i][j], BATCH, wmma::mem_col_major);
}

// ---------------------------------------------------------------------------
// Kernel 3: response contraction via wmma — warp-private W tiles, no block
// barriers in tree loop. NT=4 trees/block -> 3 CTAs/SM.
// ---------------------------------------------------------------------------
#define BT    128
#define NT    4
#define NBLK  (NTREES / NT)             // 128
#define W_LDM 72
#define R_LDM 72

#define RS_WHI 0
#define RS_WLO 18432
#define RS_RHI 36864
#define RS_RLO 46080
#define RS_TH  55296
#define RS_EI  (55296 + 128)
#define RSMEM  (55296 + 256)

__global__ __launch_bounds__(256, 3)
void resp_mma_kernel(const float* __restrict__ resp,
                     const float* __restrict__ th,
                     const float* __restrict__ lt) {
    extern __shared__ char smem[];
    __half* Whi_s = (__half*)(smem + RS_WHI);
    __half* Wlo_s = (__half*)(smem + RS_WLO);
    __half* rhi_s = (__half*)(smem + RS_RHI);
    __half* rlo_s = (__half*)(smem + RS_RLO);
    float*  th_s  = (float*)(smem + RS_TH);
    float*  ei_s  = (float*)(smem + RS_EI);

    const int tid = threadIdx.x;
    const int w   = tid >> 5;
    const int l   = tid & 31;
    const int n0  = blockIdx.x * NT;
    const int b0  = blockIdx.y * BT;

    for (int i = tid; i < NT * UNITS * LEAVES / 2; i += 256) {
        int t = i >> 9, rem2 = i & 511;
        int u = rem2 >> 5, c2 = rem2 & 31;
        float2 v = *(const float2*)(resp + (size_t)(n0 + t) * (UNITS * LEAVES) + u * 64 + c2 * 2);
        __half2 hi = __floats2half2_rn(v.x, v.y);
        __half2 lo = __floats2half2_rn(v.x - __low2float(hi), v.y - __high2float(hi));
        *(__half2*)(rhi_s + (t * UNITS + u) * R_LDM + c2 * 2) = hi;
        *(__half2*)(rlo_s + (t * UNITS + u) * R_LDM + c2 * 2) = lo;
    }
    if (tid < NT * TDEPTH) {
        th_s[tid] = th[n0 * TDEPTH + tid];
        ei_s[tid] = __expf(-lt[n0 * TDEPTH + tid]);
    }

    wmma::fragment<wmma::accumulator, 16, 16, 16, float> cfrag;
    wmma::fill_fragment(cfrag, 0.f);
    __syncthreads();

    const int rl = l & 15;
    const int h  = l >> 4;
    const int bg = b0 + w * 16 + rl;

    float fvv[TDEPTH];
#pragma unroll
    for (int d = 0; d < TDEPTH; d++)
        fvv[d] = g_fvT[(size_t)(n0 * TDEPTH + d) * BATCH + bg];

#pragma unroll 1
    for (int t = 0; t < NT; t++) {
        __syncwarp();
        {
            float gp[TDEPTH], gn[TDEPTH];
#pragma unroll
            for (int d = 0; d < TDEPTH; d++) {
                float tt = (fvv[d] - th_s[t * TDEPTH + d]) * ei_s[t * TDEPTH + d];
                gp[d] = __saturatef(fmaf(0.5f, tt, 0.5f));
                gn[d] = 1.f - gp[d];
            }
            float wlo[4];
            wlo[0] = gp[0] * gp[1];
            wlo[1] = gn[0] * gp[1];
            wlo[2] = gp[0] * gn[1];
            wlo[3] = gn[0] * gn[1];
            float g5 = h ? gn[5] : gp[5];
            float a3[4], whi8[8];
            a3[0] = gp[2] * gp[3]; a3[1] = gn[2] * gp[3];
            a3[2] = gp[2] * gn[3]; a3[3] = gn[2] * gn[3];
#pragma unroll
            for (int j = 0; j < 4; j++) {
                whi8[j]     = a3[j] * gp[4] * g5;
                whi8[j + 4] = a3[j] * gn[4] * g5;
            }

            uint32_t uhi[16], ulo[16];
#pragma unroll
            for (int j = 0; j < 8; j++) {
                float w0 = wlo[0] * whi8[j], w1 = wlo[1] * whi8[j];
                float w2 = wlo[2] * whi8[j], w3 = wlo[3] * whi8[j];
                __half2 h01 = __floats2half2_rn(w0, w1);
                __half2 h23 = __floats2half2_rn(w2, w3);
                __half2 l01 = __floats2half2_rn(w0 - __low2float(h01),
                                                w1 - __high2float(h01));
                __half2 l23 = __floats2half2_rn(w2 - __low2float(h23),
                                                w3 - __high2float(h23));
                uhi[j * 2] = h2u(h01); uhi[j * 2 + 1] = h2u(h23);
                ulo[j * 2] = h2u(l01); ulo[j * 2 + 1] = h2u(l23);
            }
            uint4* dh = (uint4*)(Whi_s + (w * 16 + rl) * W_LDM + h * 32);
            uint4* dl = (uint4*)(Wlo_s + (w * 16 + rl) * W_LDM + h * 32);
#pragma unroll
            for (int q = 0; q < 4; q++) {
                dh[q] = make_uint4(uhi[q * 4], uhi[q * 4 + 1], uhi[q * 4 + 2], uhi[q * 4 + 3]);
                dl[q] = make_uint4(ulo[q * 4], ulo[q * 4 + 1], ulo[q * 4 + 2], ulo[q * 4 + 3]);
            }
        }
        __syncwarp();

        if (t < NT - 1) {
#pragma unroll
            for (int d = 0; d < TDEPTH; d++)
                fvv[d] = g_fvT[(size_t)((n0 + t + 1) * TDEPTH + d) * BATCH + bg];
        }

        const __half* rh  = rhi_s + t * UNITS * R_LDM;
        const __half* rl2 = rlo_s + t * UNITS * R_LDM;
#pragma unroll
        for (int kk = 0; kk < LEAVES / 16; kk++) {
            wmma::fragment<wmma::matrix_a, 16, 16, 16, __half, wmma::row_major> ahi, alo;
            wmma::fragment<wmma::matrix_b, 16, 16, 16, __half, wmma::col_major> bhi, blo;
            wmma::load_matrix_sync(ahi, Whi_s + (w * 16) * W_LDM + kk * 16, W_LDM);
            wmma::load_matrix_sync(alo, Wlo_s + (w * 16) * W_LDM + kk * 16, W_LDM);
            wmma::load_matrix_sync(bhi, rh + kk * 16, R_LDM);
            wmma::load_matrix_sync(blo, rl2 + kk * 16, R_LDM);
            wmma::mma_sync(cfrag, ahi, bhi, cfrag);
            wmma::mma_sync(cfrag, alo, bhi, cfrag);
            wmma::mma_sync(cfrag, ahi, blo, cfrag);
        }
    }

    float* op = g_partial + ((size_t)blockIdx.x * BATCH + b0 + w * 16) * UNITS;
    wmma::store_matrix_sync(op, cfrag, UNITS, wmma::mem_row_major);
}

// ---------------------------------------------------------------------------
// Kernel 4a: reduction stage 1 — 512 CTAs, fully coalesced; group p sums
// partials [16p, 16p+16) for all 16384 outputs.
// ---------------------------------------------------------------------------
__global__ void reduce1_kernel() {
    int tid = blockIdx.x * blockDim.x + threadIdx.x;   // 0..131071
    int p = tid >> 14;                                 // 0..7
    int i = tid & 16383;
    const float* src = g_partial + (size_t)(p * 16) * (BATCH * UNITS) + i;
    float acc = 0.f;
#pragma unroll
    for (int k = 0; k < 16; k++)
        acc += src[(size_t)k * (BATCH * UNITS)];
    g_red[(size_t)p * (BATCH * UNITS) + i] = acc;
}

// ---------------------------------------------------------------------------
// Kernel 4b: reduction stage 2 — 8 coalesced loads per output + mean.
// ---------------------------------------------------------------------------
__global__ void reduce2_kernel(float* __restrict__ out) {
    int i = blockIdx.x * blockDim.x + threadIdx.x;     // 0..16383
    float acc = 0.f;
#pragma unroll
    for (int p = 0; p < 8; p++)
        acc += g_red[(size_t)p * (BATCH * UNITS) + i];
    out[i] = acc * (1.f / (float)NTREES);
}

// ---------------------------------------------------------------------------
extern "C" void kernel_launch(void* const* d_in, const int* in_sizes, int n_in,
                              void* d_out, int out_size) {
    const float* x    = (const float*)d_in[0];   // (1024, 256)
    const float* fsl  = (const float*)d_in[1];   // (256, 512, 6)
    const float* th   = (const float*)d_in[2];   // (512, 6)
    const float* lt   = (const float*)d_in[3];   // (512, 6)
    const float* resp = (const float*)d_in[4];   // (512, 16, 64)
    float* out = (float*)d_out;                  // (1024, 16)

    cudaFuncSetAttribute(fv_mma_kernel,
                         cudaFuncAttributeMaxDynamicSharedMemorySize, S_TOT);
    cudaFuncSetAttribute(resp_mma_kernel,
                         cudaFuncAttributeMaxDynamicSharedMemorySize, RSMEM);

    prep_kernel<<<512, 256>>>(fsl, x);
    fv_mma_kernel<<<dim3(NJ / GN, BATCH / GM), 256, S_TOT>>>();
    resp_mma_kernel<<<dim3(NBLK, BATCH / BT), 256, RSMEM>>>(resp, th, lt);
    reduce1_kernel<<<512, 256>>>();
    reduce2_kernel<<<64, 256>>>(out);
}